// round 6
// baseline (speedup 1.0000x reference)
#include <cuda_runtime.h>

// out[b,c,h,w] = max over 4 directional 3x3 Laplacians (zero-padded).
// out = max(s0,s1,s2,s3) - 2*c  (shared center term, one FFMA).
// Software pipeline: row h+2 loads while row h computes (4 rotating windows).
// Horizontal halos via warp shuffle; real loads only on warp-edge lanes.

#define W   512
#define H   512
#define RPT 8    // rows per thread

__device__ __forceinline__ void load_row6(const float* __restrict__ img,
                                          int h, int w0, int lane, float a[6]) {
    if ((unsigned)h >= (unsigned)H) {
        #pragma unroll
        for (int i = 0; i < 6; i++) a[i] = 0.f;
        return;
    }
    const float* row = img + h * W;
    float4 v = __ldg((const float4*)(row + w0));
    a[1] = v.x; a[2] = v.y; a[3] = v.z; a[4] = v.w;

    float l = __shfl_up_sync(0xffffffffu, v.w, 1);    // lane-1's .w = x[w0-1]
    float r = __shfl_down_sync(0xffffffffu, v.x, 1);  // lane+1's .x = x[w0+4]
    if (lane == 0)  l = (w0 > 0)     ? __ldg(row + w0 - 1) : 0.f;
    if (lane == 31) r = (w0 + 4 < W) ? __ldg(row + w0 + 4) : 0.f;
    a[0] = l;
    a[5] = r;
}

__global__ __launch_bounds__(128, 12)
void maxlap_kernel(const float* __restrict__ x, float* __restrict__ out) {
    const int img  = blockIdx.y;
    const int h0   = blockIdx.x * RPT;
    const int w0   = threadIdx.x * 4;   // 128 threads cover the full 512 row
    const int lane = threadIdx.x & 31;

    const float* in  = x   + (size_t)img * H * W;
    float*       dst = out + (size_t)img * H * W;

    // 4 rotating windows: at iteration rr,
    //   t = win[rr&3], m = win[(rr+1)&3], b = win[(rr+2)&3],
    //   row h0+rr+2 prefetches into win[(rr+3)&3].
    float win[4][6];
    load_row6(in, h0 - 1, w0, lane, win[0]);
    load_row6(in, h0,     w0, lane, win[1]);
    load_row6(in, h0 + 1, w0, lane, win[2]);

    #pragma unroll
    for (int rr = 0; rr < RPT; rr++) {
        if (rr < RPT - 1)
            load_row6(in, h0 + rr + 2, w0, lane, win[(rr + 3) & 3]);  // prefetch

        const float* t = win[ rr      & 3];
        const float* m = win[(rr + 1) & 3];
        const float* b = win[(rr + 2) & 3];

        float4 o;
        float* op = (float*)&o;
        #pragma unroll
        for (int i = 0; i < 4; i++) {
            const float s0 = m[i]     + m[i + 2];
            const float s1 = t[i + 1] + b[i + 1];
            const float s2 = t[i + 2] + b[i];
            const float s3 = t[i]     + b[i + 2];
            const float ms = fmaxf(fmaxf(s0, s1), fmaxf(s2, s3));
            op[i] = fmaf(-2.f, m[i + 1], ms);
        }
        *(float4*)(dst + (h0 + rr) * W + w0) = o;
    }
}

extern "C" void kernel_launch(void* const* d_in, const int* in_sizes, int n_in,
                              void* d_out, int out_size) {
    const float* x = (const float*)d_in[0];
    float* out = (float*)d_out;

    const int n_img = in_sizes[0] / (H * W);  // B*C = 48

    dim3 block(W / 4);               // 128 threads = one full row
    dim3 grid(H / RPT, n_img);       // 64 x 48 = 3072 blocks
    maxlap_kernel<<<grid, block>>>(x, out);
}

// round 7
// speedup vs baseline: 1.2959x; 1.2959x over previous
#include <cuda_runtime.h>

// out[b,c,h,w] = max over 4 directional 3x3 Laplacians (zero-padded).
// out = max(s0,s1,s2,s3) - 2*c  (shared center term -> single FFMA).
// Software pipeline: row h+2 loads while row h computes (4 rotating windows).
// RPT=16 -> grid of 1536 blocks = ONE full wave at 11 blocks/SM.

#define W   512
#define H   512
#define RPT 16   // rows per thread

__device__ __forceinline__ void load_row6(const float* __restrict__ img,
                                          int h, int w0, float a[6]) {
    if ((unsigned)h >= (unsigned)H) {
        #pragma unroll
        for (int i = 0; i < 6; i++) a[i] = 0.f;
        return;
    }
    const float* row = img + h * W;
    float4 v = __ldg((const float4*)(row + w0));
    a[1] = v.x; a[2] = v.y; a[3] = v.z; a[4] = v.w;
    a[0] = (w0 > 0)     ? __ldg(row + w0 - 1) : 0.f;  // L1/L2 hit
    a[5] = (w0 + 4 < W) ? __ldg(row + w0 + 4) : 0.f;  // L1/L2 hit
}

__global__ __launch_bounds__(128, 11)
void maxlap_kernel(const float* __restrict__ x, float* __restrict__ out) {
    const int img = blockIdx.y;
    const int h0  = blockIdx.x * RPT;
    const int w0  = threadIdx.x * 4;   // 128 threads cover the full 512 row

    const float* in  = x   + (size_t)img * H * W;
    float*       dst = out + (size_t)img * H * W;

    // 4 rotating windows: at iteration rr,
    //   t = win[rr&3], m = win[(rr+1)&3], b = win[(rr+2)&3],
    //   row h0+rr+2 prefetches into win[(rr+3)&3].
    float win[4][6];
    load_row6(in, h0 - 1, w0, win[0]);
    load_row6(in, h0,     w0, win[1]);
    load_row6(in, h0 + 1, w0, win[2]);

    #pragma unroll
    for (int rr = 0; rr < RPT; rr++) {
        if (rr < RPT - 1)
            load_row6(in, h0 + rr + 2, w0, win[(rr + 3) & 3]);  // prefetch

        const float* t = win[ rr      & 3];
        const float* m = win[(rr + 1) & 3];
        const float* b = win[(rr + 2) & 3];

        float4 o;
        float* op = (float*)&o;
        #pragma unroll
        for (int i = 0; i < 4; i++) {
            const float s0 = m[i]     + m[i + 2];
            const float s1 = t[i + 1] + b[i + 1];
            const float s2 = t[i + 2] + b[i];
            const float s3 = t[i]     + b[i + 2];
            const float ms = fmaxf(fmaxf(s0, s1), fmaxf(s2, s3));
            op[i] = fmaf(-2.f, m[i + 1], ms);
        }
        // Streaming store: don't let the output stream evict the L2-resident input.
        __stcs((float4*)(dst + (h0 + rr) * W + w0), o);
    }
}

extern "C" void kernel_launch(void* const* d_in, const int* in_sizes, int n_in,
                              void* d_out, int out_size) {
    const float* x = (const float*)d_in[0];
    float* out = (float*)d_out;

    const int n_img = in_sizes[0] / (H * W);  // B*C = 48

    dim3 block(W / 4);               // 128 threads = one full row
    dim3 grid(H / RPT, n_img);       // 32 x 48 = 1536 blocks (single wave)
    maxlap_kernel<<<grid, block>>>(x, out);
}